// round 2
// baseline (speedup 1.0000x reference)
#include <cuda_runtime.h>
#include <cuda_bf16.h>
#include <stdint.h>

#define D 512              // embedding dim (fixed by problem)
#define EPS 1e-6f

// Runtime index-dtype flag: 1 if edge_index is int64, 0 if int32.
__device__ int g_idx_is64;

// Detect dtype by inspecting the first 512 (lo, hi) 32-bit word pairs.
// int64 little-endian indices in [0, n_nodes) => hi word always 0.
// int32 => "hi" word is the next random index, ~never all zero.
__global__ void detect_idx_dtype_kernel(const int* __restrict__ raw)
{
    __shared__ int any_hi_nonzero;
    if (threadIdx.x == 0) any_hi_nonzero = 0;
    __syncthreads();
    // words 0..1023 exist in both layouts (int32 buffer has >= 300000 words)
    int lo = raw[2 * threadIdx.x];
    int hi = raw[2 * threadIdx.x + 1];
    if (hi != 0 || lo < 0) atomicOr(&any_hi_nonzero, 1);
    __syncthreads();
    if (threadIdx.x == 0) g_idx_is64 = any_hi_nonzero ? 0 : 1;
}

// One warp per edge. Each lane loads 4 float4 from row a and 4 from row b
// (coalesced, 8 independent loads in flight), accumulates dot/na2/nb2/sa/sb,
// then a 5-value butterfly reduction; lane 0 runs the scalar epilogue:
//   dist^2 = 2 - 2*dot*inva*invb + 2*eps*(sa*inva - sb*invb) + D*eps^2
//   out    = sigmoid(1 - sqrt(max(dist^2, 0)))
__global__ void __launch_bounds__(256)
edge_decoder_kernel(const float* __restrict__ z,
                    const void* __restrict__ edge_index,
                    float* __restrict__ out,
                    int n_edges)
{
    int warp_global = (blockIdx.x * blockDim.x + threadIdx.x) >> 5;
    int lane = threadIdx.x & 31;
    if (warp_global >= n_edges) return;

    long long ia, ib;
    if (g_idx_is64) {
        const long long* e = (const long long*)edge_index;
        ia = e[warp_global];
        ib = e[warp_global + n_edges];
    } else {
        const int* e = (const int*)edge_index;
        ia = e[warp_global];
        ib = e[warp_global + n_edges];
    }

    const float4* __restrict__ A =
        reinterpret_cast<const float4*>(z + ia * (long long)D);
    const float4* __restrict__ B =
        reinterpret_cast<const float4*>(z + ib * (long long)D);

    float dot = 0.f, na2 = 0.f, nb2 = 0.f, sa = 0.f, sb = 0.f;

    // 512 floats = 128 float4 per row; 32 lanes * 4 iterations.
    // Front-load all 8 loads for MLP.
    float4 av[4], bv[4];
#pragma unroll
    for (int j = 0; j < 4; j++) {
        av[j] = A[lane + 32 * j];
        bv[j] = B[lane + 32 * j];
    }
#pragma unroll
    for (int j = 0; j < 4; j++) {
        float4 a = av[j], b = bv[j];
        dot = fmaf(a.x, b.x, dot);
        dot = fmaf(a.y, b.y, dot);
        dot = fmaf(a.z, b.z, dot);
        dot = fmaf(a.w, b.w, dot);
        na2 = fmaf(a.x, a.x, na2);
        na2 = fmaf(a.y, a.y, na2);
        na2 = fmaf(a.z, a.z, na2);
        na2 = fmaf(a.w, a.w, na2);
        nb2 = fmaf(b.x, b.x, nb2);
        nb2 = fmaf(b.y, b.y, nb2);
        nb2 = fmaf(b.z, b.z, nb2);
        nb2 = fmaf(b.w, b.w, nb2);
        sa += a.x + a.y + a.z + a.w;
        sb += b.x + b.y + b.z + b.w;
    }

    // Warp butterfly reduction of 5 values
#pragma unroll
    for (int off = 16; off > 0; off >>= 1) {
        dot += __shfl_xor_sync(0xFFFFFFFFu, dot, off);
        na2 += __shfl_xor_sync(0xFFFFFFFFu, na2, off);
        nb2 += __shfl_xor_sync(0xFFFFFFFFu, nb2, off);
        sa  += __shfl_xor_sync(0xFFFFFFFFu, sa,  off);
        sb  += __shfl_xor_sync(0xFFFFFFFFu, sb,  off);
    }

    if (lane == 0) {
        float inva = rsqrtf(na2);
        float invb = rsqrtf(nb2);
        float d2 = 2.0f - 2.0f * dot * inva * invb
                 + 2.0f * EPS * (sa * inva - sb * invb)
                 + (float)D * EPS * EPS;
        d2 = fmaxf(d2, 0.0f);
        float v = 1.0f - sqrtf(d2);
        out[warp_global] = 1.0f / (1.0f + __expf(-v));
    }
}

extern "C" void kernel_launch(void* const* d_in, const int* in_sizes, int n_in,
                              void* d_out, int out_size)
{
    const float* z = (const float*)d_in[0];
    const void* edge_index = d_in[1];
    float* out = (float*)d_out;

    int n_edges = in_sizes[1] / 2;   // edge_index is [2, n_edges]

    detect_idx_dtype_kernel<<<1, 512>>>((const int*)edge_index);

    int warps_per_block = 256 / 32;  // 8 edges per block
    int grid = (n_edges + warps_per_block - 1) / warps_per_block;
    edge_decoder_kernel<<<grid, 256>>>(z, edge_index, out, n_edges);
}